// round 2
// baseline (speedup 1.0000x reference)
#include <cuda_runtime.h>
#include <cstdint>

// FuseSliceCatSameInputModule_v2: gather 8 groups of 8 disjoint 32-wide column
// slices from input [rows, 4096] fp32 into 8 outputs [rows, 256], packed
// group-major into d_out.
//
// out[g][row][c]  (c in [0,256)) = in[row][g*512 + (c/32)*64 + (c%32)]
//
// Every 32-float slice is exactly one aligned 128B line. Vectorized as float4:
// output float4 col c4 in [0,64); input float4 col = g*128 + (c4>>3)*16 + (c4&7).
// Each block handles 8 rows of one group: 256 threads x 2 float4 each.

static constexpr int IN_COLS4     = 4096 / 4;  // 1024 float4 per input row
static constexpr int OUT_COLS4    = 256 / 4;   // 64 float4 per output row per group
static constexpr int ROWS_PER_BLK = 8;         // 256 thr * 2 f4 / 64 f4-per-row

__global__ __launch_bounds__(256)
void slice_cat_kernel(const float4* __restrict__ in, float4* __restrict__ out,
                      int rows)
{
    const int t    = threadIdx.x;
    const int c4   = t & 63;                  // output float4 col within group row
    const int rsub = t >> 6;                  // 0..3
    const int g    = blockIdx.z;              // group 0..7
    const int row0 = blockIdx.x * ROWS_PER_BLK + rsub;

    const int j = c4 >> 3;   // slice index 0..7
    const int w = c4 & 7;    // float4 within slice

    const int  in_col4  = (g << 7) + (j << 4) + w;   // g*128 + j*16 + w
    const long out_base = ((long)g * rows) * OUT_COLS4;

#pragma unroll
    for (int k = 0; k < 2; ++k) {
        const int row = row0 + (k << 2);     // rsub + {0,4}
        if (row < rows) {
            out[out_base + (long)row * OUT_COLS4 + c4] =
                __ldg(&in[(long)row * IN_COLS4 + in_col4]);
        }
    }
}

extern "C" void kernel_launch(void* const* d_in, const int* in_sizes, int n_in,
                              void* d_out, int out_size)
{
    const float4* in  = (const float4*)d_in[0];
    float4*       out = (float4*)d_out;

    const int rows = in_sizes[0] / 4096;     // 16384 for the reference shape

    dim3 block(256, 1, 1);
    dim3 grid((rows + ROWS_PER_BLK - 1) / ROWS_PER_BLK, 1, 8);  // (2048, 1, 8)
    slice_cat_kernel<<<grid, block>>>(in, out, rows);
}

// round 5
// speedup vs baseline: 1.0071x; 1.0071x over previous
#include <cuda_runtime.h>
#include <cstdint>

// FuseSliceCatSameInputModule_v2: gather 8 groups of 8 disjoint 32-wide column
// slices from input [rows, 4096] fp32 into 8 outputs [rows, 256], packed
// group-major into d_out.
//
// out[g][row][c] (c in [0,256)) = in[row][g*512 + (c/32)*64 + (c%32)]
//
// Every 32-float slice is one aligned 128B line. float4-vectorized:
// input float4 col = g*128 + (c4>>3)*16 + (c4&7), c4 in [0,64).
// Each block: 16 rows of one group; 256 threads x 4 float4, loads batched
// ahead of stores (MLP=4), streaming cache hints (single-use data).

static constexpr int IN_COLS4     = 4096 / 4;  // 1024
static constexpr int OUT_COLS4    = 256 / 4;   // 64
static constexpr int ROWS_PER_BLK = 16;        // 256 thr * 4 f4 / 64 f4-per-row

__global__ __launch_bounds__(256)
void slice_cat_kernel(const float4* __restrict__ in, float4* __restrict__ out,
                      int rows)
{
    const int t    = threadIdx.x;
    const int c4   = t & 63;
    const int rsub = t >> 6;                 // 0..3
    const int g    = blockIdx.z;
    const int row0 = blockIdx.x * ROWS_PER_BLK + rsub;

    const int j = c4 >> 3;
    const int w = c4 & 7;

    const int  in_col4  = (g << 7) + (j << 4) + w;
    const long out_base = ((long)g * rows) * OUT_COLS4 + c4;

    const float4* ip = in  + (long)row0 * IN_COLS4 + in_col4;
    float4*       op = out + out_base + (long)row0 * OUT_COLS4;

    if (row0 + 12 < rows) {
        // fast path: 4 independent loads issued before any store
        float4 v0 = __ldcs(ip);
        float4 v1 = __ldcs(ip + 4L * IN_COLS4);
        float4 v2 = __ldcs(ip + 8L * IN_COLS4);
        float4 v3 = __ldcs(ip + 12L * IN_COLS4);
        __stcs(op,                    v0);
        __stcs(op + 4L * OUT_COLS4,  v1);
        __stcs(op + 8L * OUT_COLS4,  v2);
        __stcs(op + 12L * OUT_COLS4, v3);
    } else {
#pragma unroll
        for (int k = 0; k < 4; ++k) {
            const int row = row0 + (k << 2);
            if (row < rows)
                __stcs(op + (long)(k << 2) * OUT_COLS4,
                       __ldcs(ip + (long)(k << 2) * IN_COLS4));
        }
    }
}

extern "C" void kernel_launch(void* const* d_in, const int* in_sizes, int n_in,
                              void* d_out, int out_size)
{
    const float4* in  = (const float4*)d_in[0];
    float4*       out = (float4*)d_out;

    const int rows = in_sizes[0] / 4096;     // 16384 reference

    dim3 block(256, 1, 1);
    dim3 grid((rows + ROWS_PER_BLK - 1) / ROWS_PER_BLK, 1, 8);  // (1024, 1, 8)
    slice_cat_kernel<<<grid, block>>>(in, out, rows);
}